// round 2
// baseline (speedup 1.0000x reference)
#include <cuda_runtime.h>
#include <cstdint>

// ---------------- problem constants ----------------
#define B_    4
#define C_    64
#define HW_   32
#define NPIX  1024            // 32*32
#define PR    34              // padded rows actually used (0..33)
#define PSTR  36              // padded row stride in g_a (floats)
#define PLANE (PR * PSTR)     // 1224 floats per (b,c) plane
#define S_    16              // K-split factor
#define CCHUNK 4              // channels per split
#define KBLK  (CCHUNK * 9)    // 36 k-steps per block
#define APSTR 40              // As row stride in ull (2*40 = 80 words = 16-bank shift)

// ---------------- scratch (device globals; no allocation allowed) -------
__device__ float g_a1[B_ * C_ * PLANE];          // relu(bn1(x)), zero-padded
__device__ float g_a2[B_ * C_ * PLANE];          // relu(bn2(adder1)), zero-padded
__device__ float g_p1[S_ * B_ * C_ * NPIX];      // adder1 split partials (16.8 MB)
__device__ float g_p2[S_ * B_ * C_ * NPIX];      // adder2 split partials
__device__ float g_out2[B_ * C_ * NPIX];         // adder2 full output
__device__ float g_s[B_ * C_];                   // channel means
__device__ float g_g[B_ * C_];                   // SE gate

// packed fp32x2 add (Blackwell)
__device__ __forceinline__ unsigned long long f2add(unsigned long long a,
                                                    unsigned long long b) {
    unsigned long long r;
    asm("add.rn.f32x2 %0, %1, %2;" : "=l"(r) : "l"(a), "l"(b));
    return r;
}

// ---------------- BN + ReLU into zero-padded layout ----------------
__global__ void k_bnpad(const float* __restrict__ xin, int stage,
                        const float* __restrict__ gam,
                        const float* __restrict__ bet,
                        const float* __restrict__ mu,
                        const float* __restrict__ var) {
    int idx = blockIdx.x * blockDim.x + threadIdx.x;
    const int total = B_ * C_ * PLANE;
    if (idx >= total) return;
    float* outp = stage ? g_a2 : g_a1;

    int q  = idx % PSTR;
    int t  = idx / PSTR;
    int r  = t % PR;
    int bc = t / PR;

    float val = 0.f;
    if (r >= 1 && r <= 32 && q >= 1 && q <= 32) {
        int pix = bc * NPIX + (r - 1) * 32 + (q - 1);
        float s;
        if (stage) {
            s = 0.f;
#pragma unroll
            for (int sp = 0; sp < S_; sp++)
                s += g_p1[sp * (B_ * C_ * NPIX) + pix];
        } else {
            s = xin[pix];
        }
        int c = bc & (C_ - 1);
        float inv = gam[c] * rsqrtf(var[c] + 1e-5f);
        float o = s * inv + (bet[c] - mu[c] * inv);
        val = fmaxf(o, 0.f);
    }
    outp[idx] = val;
}

// ---------------- AdderNet conv, K-split, packed f32x2 ----------------
// grid: (64 pixel-tiles, 16 k-splits); block: 128 threads, 6 blocks/SM
// pixel tile = one image's 2 output rows x 32 cols (64 px) x all 64 out-ch
// thread tile = 4 px (x = pcol0 + 8i) x 8 out-ch (4 packed o-pairs)
__global__ __launch_bounds__(128, 6) void k_adder(int stage,
                                                  const float* __restrict__ w) {
    __shared__ unsigned long long As[CCHUNK * 4 * APSTR];  // splat input, 5.1 KB
    __shared__ unsigned long long Bs[KBLK * 32];           // -w o-pairs,  9.2 KB

    const float* apad = stage ? g_a2 : g_a1;
    float*       part = stage ? g_p2 : g_p1;

    int tid  = threadIdx.x;
    int bx   = blockIdx.x;           // 0..63
    int sp   = blockIdx.y;           // 0..15 (k-split)
    int b    = bx >> 4;
    int row0 = (bx & 15) * 2;        // output rows row0, row0+1
    int c0   = sp * CCHUNK;

    int og    = tid >> 4;            // 0..7  -> out channels og*8..og*8+7
    int pg    = tid & 15;
    int prow  = pg >> 3;             // 0..1
    int pcol0 = pg & 7;              // 0..7

    // stage A: 4 channels x 4 padded rows x 40 cols (zero-fill 36..39), splat
    const float* ap = apad + (b * C_ + c0) * PLANE;
    for (int i = tid; i < CCHUNK * 4 * APSTR; i += 128) {
        int cc  = i / (4 * APSTR);
        int rem = i - cc * (4 * APSTR);
        int r   = rem / APSTR;
        int q   = rem - r * APSTR;
        float v = (q < PSTR) ? ap[cc * PLANE + (row0 + r) * PSTR + q] : 0.f;
        unsigned int bits = __float_as_uint(v);
        As[i] = ((unsigned long long)bits << 32) | bits;
    }
    // stage B: negated weights, o-pairs packed
    float* Bsf = (float*)Bs;
    for (int i = tid; i < KBLK * 64; i += 128) {
        int k  = i >> 6;
        int o  = i & 63;
        int cc = k / 9;
        int t9 = k - cc * 9;                 // kh*3+kw
        Bsf[k * 64 + o] = -w[(o * C_ + c0 + cc) * 9 + t9];
    }
    __syncthreads();

    unsigned long long acc[4][4];
#pragma unroll
    for (int i = 0; i < 4; i++)
#pragma unroll
        for (int j = 0; j < 4; j++) acc[i][j] = 0ull;

    const unsigned long long ABSM = 0x7FFFFFFF7FFFFFFFULL;

#pragma unroll 1
    for (int cc = 0; cc < CCHUNK; ++cc) {
#pragma unroll
        for (int kh = 0; kh < 3; ++kh) {
            const unsigned long long* arow =
                &As[cc * (4 * APSTR) + (prow + kh) * APSTR + pcol0];
#pragma unroll
            for (int kw = 0; kw < 3; ++kw) {
                unsigned long long av[4];
#pragma unroll
                for (int i = 0; i < 4; i++) av[i] = arow[8 * i + kw];
                const unsigned long long* brow =
                    &Bs[(cc * 9 + kh * 3 + kw) * 32 + og * 4];
                unsigned long long bv[4];
#pragma unroll
                for (int j = 0; j < 4; j++) bv[j] = brow[j];
#pragma unroll
                for (int i = 0; i < 4; i++) {
#pragma unroll
                    for (int j = 0; j < 4; j++) {
                        unsigned long long d = f2add(av[i], bv[j]) & ABSM; // |a-w|
                        acc[i][j] = f2add(acc[i][j], d);
                    }
                }
            }
        }
    }

    int y = row0 + prow;
    float* pbase = part + ((sp * B_ + b) * C_ + og * 8) * NPIX + y * 32;
#pragma unroll
    for (int j = 0; j < 4; j++) {
#pragma unroll
        for (int i = 0; i < 4; i++) {
            int x = pcol0 + 8 * i;
            unsigned long long a = acc[i][j];
            pbase[(2 * j) * NPIX + x]     = -__uint_as_float((unsigned int)a);
            pbase[(2 * j + 1) * NPIX + x] = -__uint_as_float((unsigned int)(a >> 32));
        }
    }
}

// ---------------- combine adder2 partials + channel means ----------------
__global__ void k_comb_se() {
    int bc  = blockIdx.x;   // 0..255 = b*64 + c
    int tid = threadIdx.x;  // 256
    float lsum = 0.f;
    int base = bc * NPIX;
    for (int p = tid; p < NPIX; p += 256) {
        float v = 0.f;
#pragma unroll
        for (int sp = 0; sp < S_; sp++)
            v += g_p2[sp * (B_ * C_ * NPIX) + base + p];
        g_out2[base + p] = v;
        lsum += v;
    }
#pragma unroll
    for (int off = 16; off; off >>= 1)
        lsum += __shfl_xor_sync(0xffffffffu, lsum, off);
    __shared__ float ws[8];
    if ((tid & 31) == 0) ws[tid >> 5] = lsum;
    __syncthreads();
    if (tid == 0) {
        float t = 0.f;
#pragma unroll
        for (int i = 0; i < 8; i++) t += ws[i];
        g_s[bc] = t * (1.f / 1024.f);
    }
}

// ---------------- SE gate: fc1 -> relu -> fc2 -> sigmoid ----------------
__global__ void k_gate(const float* __restrict__ f1w, const float* __restrict__ f1b,
                       const float* __restrict__ f2w, const float* __restrict__ f2b) {
    __shared__ float sh[256];
    __shared__ float hh[16];
    int tid = threadIdx.x;
    sh[tid] = g_s[tid];
    __syncthreads();
    if (tid < 16) {
        int b = tid >> 2, j = tid & 3;
        float acc = f1b[j];
        for (int c = 0; c < 64; c++) acc += sh[b * 64 + c] * f1w[j * 64 + c];
        hh[tid] = fmaxf(acc, 0.f);
    }
    __syncthreads();
    int b = tid >> 6, c = tid & 63;
    float z = f2b[c];
#pragma unroll
    for (int j = 0; j < 4; j++) z += hh[b * 4 + j] * f2w[c * 4 + j];
    g_g[tid] = 1.f / (1.f + expf(-z));
}

// ---------------- final: out = out2 * g + shortcut(x) ----------------
__global__ void k_final(const float* __restrict__ x, float* __restrict__ out) {
    int idx = blockIdx.x * blockDim.x + threadIdx.x;
    if (idx >= B_ * C_ * NPIX) return;
    out[idx] = g_out2[idx] * g_g[idx >> 10] + x[idx];
}

extern "C" void kernel_launch(void* const* d_in, const int* in_sizes, int n_in,
                              void* d_out, int out_size) {
    const float* x     = (const float*)d_in[0];
    const float* bn1_g = (const float*)d_in[1];
    const float* bn1_b = (const float*)d_in[2];
    const float* bn1_m = (const float*)d_in[3];
    const float* bn1_v = (const float*)d_in[4];
    const float* w1    = (const float*)d_in[5];
    const float* bn2_g = (const float*)d_in[6];
    const float* bn2_b = (const float*)d_in[7];
    const float* bn2_m = (const float*)d_in[8];
    const float* bn2_v = (const float*)d_in[9];
    const float* w2    = (const float*)d_in[10];
    const float* fc1_w = (const float*)d_in[11];
    const float* fc1_b = (const float*)d_in[12];
    const float* fc2_w = (const float*)d_in[13];
    const float* fc2_b = (const float*)d_in[14];
    float* out = (float*)d_out;

    const int padtot = B_ * C_ * PLANE;
    dim3 ag(64, 16);

    k_bnpad<<<(padtot + 255) / 256, 256>>>(x, 0, bn1_g, bn1_b, bn1_m, bn1_v);
    k_adder<<<ag, 128>>>(0, w1);
    k_bnpad<<<(padtot + 255) / 256, 256>>>(nullptr, 1, bn2_g, bn2_b, bn2_m, bn2_v);
    k_adder<<<ag, 128>>>(1, w2);
    k_comb_se<<<256, 256>>>();
    k_gate<<<1, 256>>>(fc1_w, fc1_b, fc2_w, fc2_b);
    k_final<<<(B_ * C_ * NPIX + 255) / 256, 256>>>(x, out);
}

// round 3
// speedup vs baseline: 1.1482x; 1.1482x over previous
#include <cuda_runtime.h>
#include <cstdint>

// ---------------- problem constants ----------------
#define B_    4
#define C_    64
#define NPIX  1024            // 32*32
#define PR    34              // padded rows used (0..33)
#define PSTR  36              // padded row stride in g_a (floats)
#define PLANE (PR * PSTR)     // floats per (b,c) plane
#define S_    16              // K-split factor
#define CCHUNK 4              // channels per split
#define ASTRIDE 40            // As row stride (floats)

// ---------------- scratch (device globals) ----------------
__device__ float g_a1[B_ * C_ * PLANE];          // 2*relu(bn1(x)), zero-padded
__device__ float g_a2[B_ * C_ * PLANE];          // 2*relu(bn2(adder1)), zero-padded
__device__ float g_p1[S_ * B_ * C_ * NPIX];      // adder1 split partials (POSITIVE sums)
__device__ float g_p2[S_ * B_ * C_ * NPIX];      // adder2 split partials (POSITIVE sums)
__device__ float g_out2[B_ * C_ * NPIX];         // adder2 full output (negated)
__device__ float g_s[B_ * C_];                   // channel means
__device__ float g_g[B_ * C_];                   // SE gate

// FFMA with immediate multiplier (rt_SMSP=1 on sm_103a)
__device__ __forceinline__ float ffma_m2(float w, float a2) {
    float r;  // r = a2 - 2*w
    asm("fma.rn.f32 %0, %1, 0fC0000000, %2;" : "=f"(r) : "f"(w), "f"(a2));
    return r;
}
__device__ __forceinline__ void ffma_h(float& acc, float ad) {
    // acc += 0.5 * ad
    asm("fma.rn.f32 %0, %1, 0f3F000000, %0;" : "+f"(acc) : "f"(ad));
}

// ---------------- BN + ReLU into zero-padded layout (stores 2*value) -----
// stage==0: input = x, output = g_a1 ;  stage==1: input = -sum(g_p1), output = g_a2
__global__ void k_bnpad(const float* __restrict__ xin, int stage,
                        const float* __restrict__ gam,
                        const float* __restrict__ bet,
                        const float* __restrict__ mu,
                        const float* __restrict__ var) {
    int idx = blockIdx.x * blockDim.x + threadIdx.x;
    const int total = B_ * C_ * PLANE;
    if (idx >= total) return;
    float* outp = stage ? g_a2 : g_a1;

    int q  = idx % PSTR;
    int t  = idx / PSTR;
    int r  = t % PR;
    int bc = t / PR;

    float val = 0.f;
    if (r >= 1 && r <= 32 && q >= 1 && q <= 32) {
        int pix = bc * NPIX + (r - 1) * 32 + (q - 1);
        int c = bc & (C_ - 1);
        float inv = gam[c] * rsqrtf(var[c] + 1e-5f);
        float bias = bet[c] - mu[c] * inv;
        float o;
        if (stage) {
            float s = 0.f;
#pragma unroll
            for (int sp = 0; sp < S_; sp++)
                s += g_p1[sp * (B_ * C_ * NPIX) + pix];
            o = bias - s * inv;          // adder output is -s
        } else {
            o = xin[pix] * inv + bias;
        }
        val = 2.0f * fmaxf(o, 0.f);      // store 2*a for the FFMA-imm trick
    }
    outp[idx] = val;
}

// ---------------- AdderNet conv, K-split, scalar FFMA-imm ----------------
// grid: (64 pixel-tiles, 16 k-splits); block: 64 threads
// pixel tile = one image's 2 output rows x 32 cols (64 px), all 64 out-ch
// thread tile = 8 px (p = pcol0 + 8i) x 8 out-ch (og*8..og*8+7)
__global__ __launch_bounds__(64, 8) void k_adder(int stage,
                                                 const float* __restrict__ w) {
    __shared__ float As[CCHUNK * 4 * ASTRIDE];   // staged 2*a, 2.5 KB
    __shared__ float Bs[CCHUNK * 9 * 64];        // weights, 9 KB

    const float* apad = stage ? g_a2 : g_a1;
    float*       part = stage ? g_p2 : g_p1;

    int tid  = threadIdx.x;
    int bx   = blockIdx.x;           // 0..63
    int sp   = blockIdx.y;           // 0..15 (k-split)
    int b    = bx >> 4;
    int row0 = (bx & 15) * 2;        // output rows row0, row0+1
    int c0   = sp * CCHUNK;

    int og    = tid >> 3;            // 0..7 -> out channels og*8..og*8+7
    int pcol0 = tid & 7;             // 0..7

    // stage A: 4 channels x 4 padded rows x ASTRIDE cols (zero-fill tail)
    const float* ap = apad + (b * C_ + c0) * PLANE;
    for (int i = tid; i < CCHUNK * 4 * ASTRIDE; i += 64) {
        int cc  = i / (4 * ASTRIDE);
        int rem = i - cc * (4 * ASTRIDE);
        int r   = rem / ASTRIDE;
        int q   = rem - r * ASTRIDE;
        As[i] = (q < PSTR) ? ap[cc * PLANE + (row0 + r) * PSTR + q] : 0.f;
    }
    // stage B: weights, Bs[k][o] = w[o][c0+cc][kh][kw]
    for (int i = tid; i < CCHUNK * 9 * 64; i += 64) {
        int k  = i >> 6;                     // 0..35
        int o  = i & 63;
        int cc = k / 9;
        int t9 = k - cc * 9;
        Bs[k * 64 + o] = w[(o * C_ + c0 + cc) * 9 + t9];
    }
    __syncthreads();

    float acc[8][8];
#pragma unroll
    for (int i = 0; i < 8; i++)
#pragma unroll
        for (int j = 0; j < 8; j++) acc[i][j] = 0.f;

#pragma unroll 1
    for (int cc = 0; cc < CCHUNK; ++cc) {
#pragma unroll
        for (int kh = 0; kh < 3; ++kh) {
#pragma unroll
            for (int kw = 0; kw < 3; ++kw) {
                // weights: 8 consecutive floats, 2x float4 (broadcast in warp)
                const float4* brow = (const float4*)&Bs[(cc * 9 + kh * 3 + kw) * 64 + og * 8];
                float4 b0 = brow[0], b1 = brow[1];
                float bv[8] = {b0.x, b0.y, b0.z, b0.w, b1.x, b1.y, b1.z, b1.w};
                // inputs: 8 staged 2*a values
                float av[8];
#pragma unroll
                for (int i = 0; i < 8; i++) {
                    int r = (i >> 2) + kh;
                    int q = pcol0 + 8 * (i & 3) + kw;
                    av[i] = As[cc * (4 * ASTRIDE) + r * ASTRIDE + q];
                }
#pragma unroll
                for (int i = 0; i < 8; i++) {
#pragma unroll
                    for (int j = 0; j < 8; j++) {
                        float d2 = ffma_m2(bv[j], av[i]);   // 2(a - w)
                        ffma_h(acc[i][j], fabsf(d2));       // acc += |a-w|
                    }
                }
            }
        }
    }

    // store POSITIVE sums; consumers negate
    float* pbase = part + ((sp * B_ + b) * C_ + og * 8) * NPIX;
#pragma unroll
    for (int j = 0; j < 8; j++) {
#pragma unroll
        for (int i = 0; i < 8; i++) {
            int y = row0 + (i >> 2);
            int x = pcol0 + 8 * (i & 3);
            pbase[j * NPIX + y * 32 + x] = acc[i][j];
        }
    }
}

// ---------------- combine adder2 partials (negating) + channel means -----
__global__ void k_comb_se() {
    int bc  = blockIdx.x;   // 0..255 = b*64 + c
    int tid = threadIdx.x;  // 256
    float lsum = 0.f;
    int base = bc * NPIX;
    for (int p = tid; p < NPIX; p += 256) {
        float v = 0.f;
#pragma unroll
        for (int sp = 0; sp < S_; sp++)
            v += g_p2[sp * (B_ * C_ * NPIX) + base + p];
        v = -v;
        g_out2[base + p] = v;
        lsum += v;
    }
#pragma unroll
    for (int off = 16; off; off >>= 1)
        lsum += __shfl_xor_sync(0xffffffffu, lsum, off);
    __shared__ float ws[8];
    if ((tid & 31) == 0) ws[tid >> 5] = lsum;
    __syncthreads();
    if (tid == 0) {
        float t = 0.f;
#pragma unroll
        for (int i = 0; i < 8; i++) t += ws[i];
        g_s[bc] = t * (1.f / 1024.f);
    }
}

// ---------------- SE gate: fc1 -> relu -> fc2 -> sigmoid ----------------
__global__ void k_gate(const float* __restrict__ f1w, const float* __restrict__ f1b,
                       const float* __restrict__ f2w, const float* __restrict__ f2b) {
    __shared__ float sh[256];
    __shared__ float hh[16];
    int tid = threadIdx.x;
    sh[tid] = g_s[tid];
    __syncthreads();
    if (tid < 16) {
        int b = tid >> 2, j = tid & 3;
        float acc = f1b[j];
        for (int c = 0; c < 64; c++) acc += sh[b * 64 + c] * f1w[j * 64 + c];
        hh[tid] = fmaxf(acc, 0.f);
    }
    __syncthreads();
    int b = tid >> 6, c = tid & 63;
    float z = f2b[c];
#pragma unroll
    for (int j = 0; j < 4; j++) z += hh[b * 4 + j] * f2w[c * 4 + j];
    g_g[tid] = 1.f / (1.f + expf(-z));
}

// ---------------- final: out = out2 * g + shortcut(x) ----------------
__global__ void k_final(const float* __restrict__ x, float* __restrict__ out) {
    int idx = blockIdx.x * blockDim.x + threadIdx.x;
    if (idx >= B_ * C_ * NPIX) return;
    out[idx] = g_out2[idx] * g_g[idx >> 10] + x[idx];
}

extern "C" void kernel_launch(void* const* d_in, const int* in_sizes, int n_in,
                              void* d_out, int out_size) {
    const float* x     = (const float*)d_in[0];
    const float* bn1_g = (const float*)d_in[1];
    const float* bn1_b = (const float*)d_in[2];
    const float* bn1_m = (const float*)d_in[3];
    const float* bn1_v = (const float*)d_in[4];
    const float* w1    = (const float*)d_in[5];
    const float* bn2_g = (const float*)d_in[6];
    const float* bn2_b = (const float*)d_in[7];
    const float* bn2_m = (const float*)d_in[8];
    const float* bn2_v = (const float*)d_in[9];
    const float* w2    = (const float*)d_in[10];
    const float* fc1_w = (const float*)d_in[11];
    const float* fc1_b = (const float*)d_in[12];
    const float* fc2_w = (const float*)d_in[13];
    const float* fc2_b = (const float*)d_in[14];
    float* out = (float*)d_out;

    const int padtot = B_ * C_ * PLANE;
    dim3 ag(64, 16);

    k_bnpad<<<(padtot + 255) / 256, 256>>>(x, 0, bn1_g, bn1_b, bn1_m, bn1_v);
    k_adder<<<ag, 64>>>(0, w1);
    k_bnpad<<<(padtot + 255) / 256, 256>>>(nullptr, 1, bn2_g, bn2_b, bn2_m, bn2_v);
    k_adder<<<ag, 64>>>(1, w2);
    k_comb_se<<<256, 256>>>();
    k_gate<<<1, 256>>>(fc1_w, fc1_b, fc2_w, fc2_b);
    k_final<<<(B_ * C_ * NPIX + 255) / 256, 256>>>(x, out);
}

// round 4
// speedup vs baseline: 1.1648x; 1.0145x over previous
#include <cuda_runtime.h>
#include <cstdint>

// ---------------- problem constants ----------------
#define B_    4
#define C_    64
#define NPIX  1024            // 32*32
#define PR    34              // padded rows used (0..33)
#define PSTR  36              // padded row stride in g_a (floats)
#define PLANE (PR * PSTR)     // floats per (b,c) plane
#define S_    16              // K-split factor
#define CCHUNK 4              // channels per split
#define ASTRIDE 40            // As row stride (floats)

// ---------------- scratch (device globals) ----------------
__device__ float g_a1[B_ * C_ * PLANE];          // 2*relu(bn1(x)), zero-padded
__device__ float g_a2[B_ * C_ * PLANE];          // 2*relu(bn2(adder1)), zero-padded
__device__ float g_p1[S_ * B_ * C_ * NPIX];      // adder1 partials: sum |2(a-w)|
__device__ float g_p2[S_ * B_ * C_ * NPIX];      // adder2 partials: sum |2(a-w)|
__device__ float g_out2[B_ * C_ * NPIX];         // adder2 full output (true value)
__device__ float g_s[B_ * C_];                   // channel means
__device__ float g_g[B_ * C_];                   // SE gate

// d = a2 - 2*w  (FFMA with immediate multiplier: rt_SMSP=1 on sm_103a)
__device__ __forceinline__ float ffma_m2(float w, float a2) {
    float r;
    asm("fma.rn.f32 %0, %1, 0fC0000000, %2;" : "=f"(r) : "f"(w), "f"(a2));
    return r;
}

// ---------------- BN + ReLU into zero-padded layout (stores 2*value) -----
// stage==0: input = x, output = g_a1
// stage==1: input = -(1/2)*sum(g_p1), output = g_a2
__global__ void k_bnpad(const float* __restrict__ xin, int stage,
                        const float* __restrict__ gam,
                        const float* __restrict__ bet,
                        const float* __restrict__ mu,
                        const float* __restrict__ var) {
    int idx = blockIdx.x * blockDim.x + threadIdx.x;
    const int total = B_ * C_ * PLANE;
    if (idx >= total) return;
    float* outp = stage ? g_a2 : g_a1;

    int q  = idx % PSTR;
    int t  = idx / PSTR;
    int r  = t % PR;
    int bc = t / PR;

    float val = 0.f;
    if (r >= 1 && r <= 32 && q >= 1 && q <= 32) {
        int pix = bc * NPIX + (r - 1) * 32 + (q - 1);
        int c = bc & (C_ - 1);
        float inv = gam[c] * rsqrtf(var[c] + 1e-5f);
        float bias = bet[c] - mu[c] * inv;
        float o;
        if (stage) {
            float s = 0.f;
#pragma unroll
            for (int sp = 0; sp < S_; sp++)
                s += g_p1[sp * (B_ * C_ * NPIX) + pix];
            // adder1 true output = -s/2 ; bn: o = (-s/2)*inv + bias
            o = bias - s * (0.5f * inv);
        } else {
            o = xin[pix] * inv + bias;
        }
        val = 2.0f * fmaxf(o, 0.f);      // store 2*a for the FFMA-imm trick
    }
    outp[idx] = val;
}

// ---------------- AdderNet conv, K-split, scalar FFMA-imm + FADD|.| ------
// grid: (64 pixel-tiles, 16 k-splits); block: 128 threads (4 warps)
// pixel tile = one image's 2 output rows x 32 cols (64 px), all 64 out-ch
// thread tile = 8 px (2 rows x cols pcol0+8i) x 4 out-ch (og*4..og*4+3)
__global__ __launch_bounds__(128, 7) void k_adder(int stage,
                                                  const float* __restrict__ w) {
    __shared__ float As[CCHUNK * 4 * ASTRIDE];   // staged 2*a, 2.5 KB
    __shared__ float Bs[CCHUNK * 9 * 64];        // weights, 9 KB

    const float* apad = stage ? g_a2 : g_a1;
    float*       part = stage ? g_p2 : g_p1;

    int tid  = threadIdx.x;
    int bx   = blockIdx.x;           // 0..63
    int sp   = blockIdx.y;           // 0..15 (k-split)
    int b    = bx >> 4;
    int row0 = (bx & 15) * 2;        // output rows row0, row0+1
    int c0   = sp * CCHUNK;

    int og    = tid >> 3;            // 0..15 -> out channels og*4..og*4+3
    int pcol0 = tid & 7;             // 0..7

    // stage A: 4 channels x 4 padded rows x ASTRIDE cols (zero-fill tail)
    const float* ap = apad + (b * C_ + c0) * PLANE;
    for (int i = tid; i < CCHUNK * 4 * ASTRIDE; i += 128) {
        int cc  = i / (4 * ASTRIDE);
        int rem = i - cc * (4 * ASTRIDE);
        int r   = rem / ASTRIDE;
        int q   = rem - r * ASTRIDE;
        As[i] = (q < PSTR) ? ap[cc * PLANE + (row0 + r) * PSTR + q] : 0.f;
    }
    // stage B: weights, Bs[k][o] = w[o][c0+cc][kh][kw]
    for (int i = tid; i < CCHUNK * 9 * 64; i += 128) {
        int k  = i >> 6;                     // 0..35
        int o  = i & 63;
        int cc = k / 9;
        int t9 = k - cc * 9;
        Bs[k * 64 + o] = w[(o * C_ + c0 + cc) * 9 + t9];
    }
    __syncthreads();

    float acc[8][4];
#pragma unroll
    for (int i = 0; i < 8; i++)
#pragma unroll
        for (int j = 0; j < 4; j++) acc[i][j] = 0.f;

#pragma unroll 1
    for (int cc = 0; cc < CCHUNK; ++cc) {
#pragma unroll
        for (int kh = 0; kh < 3; ++kh) {
#pragma unroll
            for (int kw = 0; kw < 3; ++kw) {
                // weights: 4 consecutive floats (8-lane broadcast)
                float4 bq = *(const float4*)&Bs[(cc * 9 + kh * 3 + kw) * 64 + og * 4];
                float bv[4] = {bq.x, bq.y, bq.z, bq.w};
                // inputs: 8 staged 2*a values
                float av[8];
#pragma unroll
                for (int i = 0; i < 8; i++) {
                    int r = (i >> 2) + kh;
                    int q = pcol0 + 8 * (i & 3) + kw;
                    av[i] = As[cc * (4 * ASTRIDE) + r * ASTRIDE + q];
                }
#pragma unroll
                for (int i = 0; i < 8; i++) {
#pragma unroll
                    for (int j = 0; j < 4; j++) {
                        float d2 = ffma_m2(bv[j], av[i]);   // 2(a - w)
                        acc[i][j] += fabsf(d2);             // FADD with |src|
                    }
                }
            }
        }
    }

    // store raw positive sums of |2(a-w)|; consumers apply the -1/2 factor
    float* pbase = part + ((sp * B_ + b) * C_ + og * 4) * NPIX;
#pragma unroll
    for (int j = 0; j < 4; j++) {
#pragma unroll
        for (int i = 0; i < 8; i++) {
            int y = row0 + (i >> 2);
            int x = pcol0 + 8 * (i & 3);
            pbase[j * NPIX + y * 32 + x] = acc[i][j];
        }
    }
}

// ---------------- combine adder2 partials (x -1/2) + channel means -------
__global__ void k_comb_se() {
    int bc  = blockIdx.x;   // 0..255 = b*64 + c
    int tid = threadIdx.x;  // 256
    float lsum = 0.f;
    int base = bc * NPIX;
    for (int p = tid; p < NPIX; p += 256) {
        float v = 0.f;
#pragma unroll
        for (int sp = 0; sp < S_; sp++)
            v += g_p2[sp * (B_ * C_ * NPIX) + base + p];
        v = -0.5f * v;
        g_out2[base + p] = v;
        lsum += v;
    }
#pragma unroll
    for (int off = 16; off; off >>= 1)
        lsum += __shfl_xor_sync(0xffffffffu, lsum, off);
    __shared__ float ws[8];
    if ((tid & 31) == 0) ws[tid >> 5] = lsum;
    __syncthreads();
    if (tid == 0) {
        float t = 0.f;
#pragma unroll
        for (int i = 0; i < 8; i++) t += ws[i];
        g_s[bc] = t * (1.f / 1024.f);
    }
}

// ---------------- SE gate: fc1 -> relu -> fc2 -> sigmoid ----------------
__global__ void k_gate(const float* __restrict__ f1w, const float* __restrict__ f1b,
                       const float* __restrict__ f2w, const float* __restrict__ f2b) {
    __shared__ float sh[256];
    __shared__ float hh[16];
    int tid = threadIdx.x;
    sh[tid] = g_s[tid];
    __syncthreads();
    if (tid < 16) {
        int b = tid >> 2, j = tid & 3;
        float acc = f1b[j];
        for (int c = 0; c < 64; c++) acc += sh[b * 64 + c] * f1w[j * 64 + c];
        hh[tid] = fmaxf(acc, 0.f);
    }
    __syncthreads();
    int b = tid >> 6, c = tid & 63;
    float z = f2b[c];
#pragma unroll
    for (int j = 0; j < 4; j++) z += hh[b * 4 + j] * f2w[c * 4 + j];
    g_g[tid] = 1.f / (1.f + expf(-z));
}

// ---------------- final: out = out2 * g + shortcut(x) ----------------
__global__ void k_final(const float* __restrict__ x, float* __restrict__ out) {
    int idx = blockIdx.x * blockDim.x + threadIdx.x;
    if (idx >= B_ * C_ * NPIX) return;
    out[idx] = g_out2[idx] * g_g[idx >> 10] + x[idx];
}

extern "C" void kernel_launch(void* const* d_in, const int* in_sizes, int n_in,
                              void* d_out, int out_size) {
    const float* x     = (const float*)d_in[0];
    const float* bn1_g = (const float*)d_in[1];
    const float* bn1_b = (const float*)d_in[2];
    const float* bn1_m = (const float*)d_in[3];
    const float* bn1_v = (const float*)d_in[4];
    const float* w1    = (const float*)d_in[5];
    const float* bn2_g = (const float*)d_in[6];
    const float* bn2_b = (const float*)d_in[7];
    const float* bn2_m = (const float*)d_in[8];
    const float* bn2_v = (const float*)d_in[9];
    const float* w2    = (const float*)d_in[10];
    const float* fc1_w = (const float*)d_in[11];
    const float* fc1_b = (const float*)d_in[12];
    const float* fc2_w = (const float*)d_in[13];
    const float* fc2_b = (const float*)d_in[14];
    float* out = (float*)d_out;

    const int padtot = B_ * C_ * PLANE;
    dim3 ag(64, 16);

    k_bnpad<<<(padtot + 255) / 256, 256>>>(x, 0, bn1_g, bn1_b, bn1_m, bn1_v);
    k_adder<<<ag, 128>>>(0, w1);
    k_bnpad<<<(padtot + 255) / 256, 256>>>(nullptr, 1, bn2_g, bn2_b, bn2_m, bn2_v);
    k_adder<<<ag, 128>>>(1, w2);
    k_comb_se<<<256, 256>>>();
    k_gate<<<1, 256>>>(fc1_w, fc1_b, fc2_w, fc2_b);
    k_final<<<(B_ * C_ * NPIX + 255) / 256, 256>>>(x, out);
}